// round 7
// baseline (speedup 1.0000x reference)
#include <cuda_runtime.h>
#include <math.h>

#define BB   4
#define CC   2048
#define DD   512
#define NHH  8
#define MTOT (BB * CC)      // 8192
#define HD   (NHH * DD)     // 4096

// ---------------- scratch (device globals: no allocation allowed) ----------------
__device__ float g_Q[(size_t)NHH * BB * CC * DD];   // [h][b][c][d]  134MB
__device__ float g_K[(size_t)NHH * BB * CC * DD];
__device__ float g_V[(size_t)NHH * BB * CC * DD];
__device__ float g_S[(size_t)NHH * BB * CC * CC];   // [hb][q][k]    536MB
__device__ float g_O[(size_t)MTOT * HD];            // [b*C+c][h*D+d] 134MB
__device__ float g_ctab[CC * (DD / 2)];
__device__ float g_stab[CC * (DD / 2)];

// ---------------- RoPE cos/sin table ----------------
// theta_i = 10000^(-2i/D); angle reduced in fp64 so large-position angles stay
// accurate (reference computes in fp32; worst-case deviation ~1e-4 absolute).
__global__ void rope_table_kernel() {
    int idx = blockIdx.x * blockDim.x + threadIdx.x;
    if (idx >= CC * (DD / 2)) return;
    int c = idx / (DD / 2);
    int i = idx - c * (DD / 2);
    double theta = exp((-2.0 * (double)i / (double)DD) * log(10000.0));
    double ang = fmod((double)c * theta, 6.283185307179586476925287);
    float af = (float)ang;
    g_ctab[idx] = cosf(af);
    g_stab[idx] = sinf(af);
}

// ---------------- shared 128x128x8 SIMT GEMM core ----------------
__device__ __forceinline__ void mm8(const float As[8][128], const float Bs[8][128],
                                    float acc[8][8], int ty8, int tx8) {
#pragma unroll
    for (int k = 0; k < 8; ++k) {
        float a[8], b[8];
        *(float4*)(a)     = *(const float4*)&As[k][ty8];
        *(float4*)(a + 4) = *(const float4*)&As[k][ty8 + 4];
        *(float4*)(b)     = *(const float4*)&Bs[k][tx8];
        *(float4*)(b + 4) = *(const float4*)&Bs[k][tx8 + 4];
#pragma unroll
        for (int i = 0; i < 8; ++i)
#pragma unroll
            for (int j = 0; j < 8; ++j)
                acc[i][j] += a[i] * b[j];
    }
}

// ---------------- Kernel 1: QKV projection + bias + RoPE ----------------
// grid: (N/128=4, M/128=64, 24)  z = h*3 + t   (t: 0=Q, 1=K, 2=V)
__global__ __launch_bounds__(256, 2)
void qkv_kernel(const float* __restrict__ x,
                const float* __restrict__ wq, const float* __restrict__ bq,
                const float* __restrict__ wk, const float* __restrict__ bk,
                const float* __restrict__ wv, const float* __restrict__ bv) {
    __shared__ float As[8][128];
    __shared__ float Bs[8][128];

    int z = blockIdx.z;
    int h = z / 3, t = z - 3 * h;
    const float* W;  const float* bias;  float* Out;
    if (t == 0)      { W = wq; bias = bq; Out = g_Q; }
    else if (t == 1) { W = wk; bias = bk; Out = g_K; }
    else             { W = wv; bias = bv; Out = g_V; }
    W    += (size_t)h * DD * DD;
    bias += h * DD;
    Out  += (size_t)h * MTOT * DD;

    const int m0 = blockIdx.y * 128;
    const int n0 = blockIdx.x * 128;
    const int tid = threadIdx.x;
    const int ty8 = (tid >> 4) * 8, tx8 = (tid & 15) * 8;
    const int ar = tid >> 1, ak = (tid & 1) * 4;   // A loader (transposed store)
    const int br = tid >> 5, bn = (tid & 31) * 4;  // B loader

    float acc[8][8];
#pragma unroll
    for (int i = 0; i < 8; ++i)
#pragma unroll
        for (int j = 0; j < 8; ++j) acc[i][j] = 0.f;

    float4 av  = *(const float4*)(x + (size_t)(m0 + ar) * DD + ak);
    float4 bv4 = *(const float4*)(W + (size_t)br * DD + n0 + bn);

    for (int kk = 0; kk < DD; kk += 8) {
        As[ak + 0][ar] = av.x; As[ak + 1][ar] = av.y;
        As[ak + 2][ar] = av.z; As[ak + 3][ar] = av.w;
        *(float4*)&Bs[br][bn] = bv4;
        __syncthreads();
        if (kk + 8 < DD) {
            av  = *(const float4*)(x + (size_t)(m0 + ar) * DD + (kk + 8) + ak);
            bv4 = *(const float4*)(W + (size_t)(kk + 8 + br) * DD + n0 + bn);
        }
        mm8(As, Bs, acc, ty8, tx8);
        __syncthreads();
    }

    float bcol[8];
    *(float4*)(bcol)     = *(const float4*)(bias + n0 + tx8);
    *(float4*)(bcol + 4) = *(const float4*)(bias + n0 + tx8 + 4);

#pragma unroll
    for (int i = 0; i < 8; ++i) {
        int m = m0 + ty8 + i;
        float o[8];
#pragma unroll
        for (int j = 0; j < 8; ++j) o[j] = acc[i][j] + bcol[j];
        if (t < 2) {  // RoPE on Q and K
            int c = m & (CC - 1);
            const float* ct = g_ctab + c * (DD / 2) + ((n0 + tx8) >> 1);
            const float* st = g_stab + c * (DD / 2) + ((n0 + tx8) >> 1);
#pragma unroll
            for (int p = 0; p < 4; ++p) {
                float cs = ct[p], sn = st[p];
                float e = o[2 * p], od = o[2 * p + 1];
                o[2 * p]     = e * cs - od * sn;
                o[2 * p + 1] = e * sn + od * cs;
            }
        }
        float* op = Out + (size_t)m * DD + n0 + tx8;
        *(float4*)(op)     = *(float4*)(o);
        *(float4*)(op + 4) = *(float4*)(o + 4);
    }
}

// ---------------- Kernel 2: S = Q K^T * scale (causal tiles only) ----------------
// grid: (kt=16, qt=16, hb=32); upper tiles early-exit.
__global__ __launch_bounds__(256, 2)
void scores_kernel() {
    int hb = blockIdx.z, qt = blockIdx.y, kt = blockIdx.x;
    if (kt > qt) return;
    __shared__ float As[8][128];
    __shared__ float Bs[8][128];

    const float* Qp = g_Q + (size_t)hb * CC * DD;
    const float* Kp = g_K + (size_t)hb * CC * DD;
    float* Sp = g_S + (size_t)hb * CC * CC;

    const int m0 = qt * 128, n0 = kt * 128;
    const int tid = threadIdx.x;
    const int ty8 = (tid >> 4) * 8, tx8 = (tid & 15) * 8;
    const int ar = tid >> 1, ak = (tid & 1) * 4;

    float acc[8][8];
#pragma unroll
    for (int i = 0; i < 8; ++i)
#pragma unroll
        for (int j = 0; j < 8; ++j) acc[i][j] = 0.f;

    float4 av  = *(const float4*)(Qp + (size_t)(m0 + ar) * DD + ak);
    float4 bv4 = *(const float4*)(Kp + (size_t)(n0 + ar) * DD + ak);

    for (int kk = 0; kk < DD; kk += 8) {
        As[ak + 0][ar] = av.x;  As[ak + 1][ar] = av.y;
        As[ak + 2][ar] = av.z;  As[ak + 3][ar] = av.w;
        Bs[ak + 0][ar] = bv4.x; Bs[ak + 1][ar] = bv4.y;
        Bs[ak + 2][ar] = bv4.z; Bs[ak + 3][ar] = bv4.w;
        __syncthreads();
        if (kk + 8 < DD) {
            av  = *(const float4*)(Qp + (size_t)(m0 + ar) * DD + (kk + 8) + ak);
            bv4 = *(const float4*)(Kp + (size_t)(n0 + ar) * DD + (kk + 8) + ak);
        }
        mm8(As, Bs, acc, ty8, tx8);
        __syncthreads();
    }

    const float scale = 0.04419417382415922f;  // 1/sqrt(512)
#pragma unroll
    for (int i = 0; i < 8; ++i) {
        int q = m0 + ty8 + i;
        float o[8];
#pragma unroll
        for (int j = 0; j < 8; ++j) {
            int kp = n0 + tx8 + j;
            o[j] = (kp <= q) ? acc[i][j] * scale : -1e30f;
        }
        float* sp = Sp + (size_t)q * CC + n0 + tx8;
        *(float4*)(sp)     = *(float4*)(o);
        *(float4*)(sp + 4) = *(float4*)(o + 4);
    }
}

// ---------------- Kernel 3: row softmax (tile-aligned length) ----------------
// grid: (C, 32), 256 threads; row kept in registers (<=8 elems/thread).
__global__ __launch_bounds__(256)
void softmax_kernel() {
    int q = blockIdx.x, hb = blockIdx.y;
    float* row = g_S + (size_t)hb * CC * CC + (size_t)q * CC;
    int L = ((q >> 7) + 1) << 7;
    int tid = threadIdx.x;

    float v[8];
    float mx = -3.4e38f;
#pragma unroll
    for (int u = 0; u < 8; ++u) {
        int idx = tid + u * 256;
        float t = (idx < L) ? row[idx] : -3.4e38f;
        v[u] = t;
        mx = fmaxf(mx, t);
    }

    __shared__ float red[256];
    red[tid] = mx; __syncthreads();
    for (int o = 128; o > 0; o >>= 1) {
        if (tid < o) red[tid] = fmaxf(red[tid], red[tid + o]);
        __syncthreads();
    }
    mx = red[0];
    __syncthreads();

    float s = 0.f;
#pragma unroll
    for (int u = 0; u < 8; ++u) {
        float e = expf(v[u] - mx);   // masked (-1e30) and OOB lanes -> 0
        v[u] = e;
        s += e;
    }
    red[tid] = s; __syncthreads();
    for (int o = 128; o > 0; o >>= 1) {
        if (tid < o) red[tid] += red[tid + o];
        __syncthreads();
    }
    float inv = 1.0f / red[0];

#pragma unroll
    for (int u = 0; u < 8; ++u) {
        int idx = tid + u * 256;
        if (idx < L) row[idx] = v[u] * inv;
    }
}

// ---------------- Kernel 4: O = P @ V (K extent per q-tile) ----------------
// grid: (nt=4, qt=16, hb=32)
__global__ __launch_bounds__(256, 2)
void pv_kernel() {
    __shared__ float As[8][128];
    __shared__ float Bs[8][128];

    int hb = blockIdx.z, qt = blockIdx.y, nt = blockIdx.x;
    const float* P  = g_S + (size_t)hb * CC * CC;
    const float* Vp = g_V + (size_t)hb * CC * DD;

    const int m0 = qt * 128, n0 = nt * 128;
    const int kmax = (qt + 1) * 128;
    const int tid = threadIdx.x;
    const int ty8 = (tid >> 4) * 8, tx8 = (tid & 15) * 8;
    const int ar = tid >> 1, ak = (tid & 1) * 4;
    const int br = tid >> 5, bn = (tid & 31) * 4;

    float acc[8][8];
#pragma unroll
    for (int i = 0; i < 8; ++i)
#pragma unroll
        for (int j = 0; j < 8; ++j) acc[i][j] = 0.f;

    float4 av  = *(const float4*)(P  + (size_t)(m0 + ar) * CC + ak);
    float4 bv4 = *(const float4*)(Vp + (size_t)br * DD + n0 + bn);

    for (int kk = 0; kk < kmax; kk += 8) {
        As[ak + 0][ar] = av.x; As[ak + 1][ar] = av.y;
        As[ak + 2][ar] = av.z; As[ak + 3][ar] = av.w;
        *(float4*)&Bs[br][bn] = bv4;
        __syncthreads();
        if (kk + 8 < kmax) {
            av  = *(const float4*)(P  + (size_t)(m0 + ar) * CC + (kk + 8) + ak);
            bv4 = *(const float4*)(Vp + (size_t)(kk + 8 + br) * DD + n0 + bn);
        }
        mm8(As, Bs, acc, ty8, tx8);
        __syncthreads();
    }

    int h = hb >> 2, b = hb & 3;   // hb = h*B + b
#pragma unroll
    for (int i = 0; i < 8; ++i) {
        int m = m0 + ty8 + i;
        float* op = g_O + (size_t)(b * CC + m) * HD + (size_t)h * DD + n0 + tx8;
        float o[8];
#pragma unroll
        for (int j = 0; j < 8; ++j) o[j] = acc[i][j];
        *(float4*)(op)     = *(float4*)(o);
        *(float4*)(op + 4) = *(float4*)(o + 4);
    }
}

// ---------------- Kernel 5: final projection [8192,4096]@[4096,512] + bo ----------------
// grid: (4, 64)
__global__ __launch_bounds__(256, 2)
void outproj_kernel(const float* __restrict__ wo, const float* __restrict__ bo,
                    float* __restrict__ out) {
    __shared__ float As[8][128];
    __shared__ float Bs[8][128];

    const int m0 = blockIdx.y * 128;
    const int n0 = blockIdx.x * 128;
    const int tid = threadIdx.x;
    const int ty8 = (tid >> 4) * 8, tx8 = (tid & 15) * 8;
    const int ar = tid >> 1, ak = (tid & 1) * 4;
    const int br = tid >> 5, bn = (tid & 31) * 4;

    float acc[8][8];
#pragma unroll
    for (int i = 0; i < 8; ++i)
#pragma unroll
        for (int j = 0; j < 8; ++j) acc[i][j] = 0.f;

    float4 av  = *(const float4*)(g_O + (size_t)(m0 + ar) * HD + ak);
    float4 bv4 = *(const float4*)(wo  + (size_t)br * DD + n0 + bn);

    for (int kk = 0; kk < HD; kk += 8) {
        As[ak + 0][ar] = av.x; As[ak + 1][ar] = av.y;
        As[ak + 2][ar] = av.z; As[ak + 3][ar] = av.w;
        *(float4*)&Bs[br][bn] = bv4;
        __syncthreads();
        if (kk + 8 < HD) {
            av  = *(const float4*)(g_O + (size_t)(m0 + ar) * HD + (kk + 8) + ak);
            bv4 = *(const float4*)(wo  + (size_t)(kk + 8 + br) * DD + n0 + bn);
        }
        mm8(As, Bs, acc, ty8, tx8);
        __syncthreads();
    }

    float bcol[8];
    *(float4*)(bcol)     = *(const float4*)(bo + n0 + tx8);
    *(float4*)(bcol + 4) = *(const float4*)(bo + n0 + tx8 + 4);

#pragma unroll
    for (int i = 0; i < 8; ++i) {
        int m = m0 + ty8 + i;
        float o[8];
#pragma unroll
        for (int j = 0; j < 8; ++j) o[j] = acc[i][j] + bcol[j];
        float* op = out + (size_t)m * DD + n0 + tx8;
        *(float4*)(op)     = *(float4*)(o);
        *(float4*)(op + 4) = *(float4*)(o + 4);
    }
}

// ---------------- launch ----------------
extern "C" void kernel_launch(void* const* d_in, const int* in_sizes, int n_in,
                              void* d_out, int out_size) {
    (void)in_sizes; (void)n_in; (void)out_size;
    const float* x  = (const float*)d_in[0];
    const float* wq = (const float*)d_in[1];
    const float* bq = (const float*)d_in[2];
    const float* wk = (const float*)d_in[3];
    const float* bk = (const float*)d_in[4];
    const float* wv = (const float*)d_in[5];
    const float* bv = (const float*)d_in[6];
    const float* wo = (const float*)d_in[7];
    const float* bo = (const float*)d_in[8];
    float* out = (float*)d_out;

    rope_table_kernel<<<(CC * (DD / 2) + 255) / 256, 256>>>();
    qkv_kernel<<<dim3(4, 64, 24), 256>>>(x, wq, bq, wk, bk, wv, bv);
    scores_kernel<<<dim3(16, 16, 32), 256>>>();
    softmax_kernel<<<dim3(CC, 32), 256>>>();
    pv_kernel<<<dim3(4, 16, 32), 256>>>();
    outproj_kernel<<<dim3(4, 64, 1), 256>>>(wo, bo, out);
}

// round 8
// speedup vs baseline: 2.6469x; 2.6469x over previous
#include <cuda_runtime.h>
#include <math.h>
#include <stdint.h>

#define BB   4
#define CC   2048
#define DD   512
#define NHH  8
#define MTOT (BB * CC)      // 8192
#define HD   (NHH * DD)     // 4096

// ---------------- scratch (device globals: no allocation allowed) ----------------
__device__ float g_Q[(size_t)NHH * BB * CC * DD];   // [h][b][c][d]
__device__ float g_K[(size_t)NHH * BB * CC * DD];
__device__ float g_V[(size_t)NHH * BB * CC * DD];
__device__ float g_S[(size_t)NHH * BB * CC * CC];   // [hb][q][k]
__device__ float g_O[(size_t)MTOT * HD];            // [b*C+c][h*D+d]
__device__ float g_ctab[CC * (DD / 2)];
__device__ float g_stab[CC * (DD / 2)];

// ---------------- RoPE cos/sin table ----------------
__global__ void rope_table_kernel() {
    int idx = blockIdx.x * blockDim.x + threadIdx.x;
    if (idx >= CC * (DD / 2)) return;
    int c = idx / (DD / 2);
    int i = idx - c * (DD / 2);
    double theta = exp((-2.0 * (double)i / (double)DD) * log(10000.0));
    double ang = fmod((double)c * theta, 6.283185307179586476925287);
    float af = (float)ang;
    g_ctab[idx] = cosf(af);
    g_stab[idx] = sinf(af);
}

// ---------------- TF32 helpers ----------------
__device__ __forceinline__ float to_tf32(float x) {
    uint32_t u;
    asm("cvt.rna.tf32.f32 %0, %1;" : "=r"(u) : "f"(x));
    return __uint_as_float(u);
}
__device__ __forceinline__ float4 to_tf32_4(float4 v) {
    return make_float4(to_tf32(v.x), to_tf32(v.y), to_tf32(v.z), to_tf32(v.w));
}

__device__ __forceinline__ void mma8(float* d, const float* a, const float* b) {
    asm volatile(
        "mma.sync.aligned.m16n8k8.row.col.f32.tf32.tf32.f32 "
        "{%0,%1,%2,%3}, {%4,%5,%6,%7}, {%8,%9}, {%0,%1,%2,%3};"
        : "+f"(d[0]), "+f"(d[1]), "+f"(d[2]), "+f"(d[3])
        : "r"(__float_as_uint(a[0])), "r"(__float_as_uint(a[1])),
          "r"(__float_as_uint(a[2])), "r"(__float_as_uint(a[3])),
          "r"(__float_as_uint(b[0])), "r"(__float_as_uint(b[1])));
}

// =====================================================================
// GEMM core, B k-major (B stored [k][n], n contiguous).
// Block tile 128x128, 256 threads, 8 warps as 2(m) x 4(n), warp tile 64x32.
// As: [2][128][20] row-major (k contiguous), Bs: [2][16][136].
// =====================================================================
__device__ __forceinline__ void gemm_bk(
    const float* __restrict__ Ag, int lda,
    const float* __restrict__ Bg, int ldb,
    int ktiles, float (&acc)[4][4][4],
    float (&As)[2][128][20], float (&Bs)[2][16][136])
{
    const int tid  = threadIdx.x;
    const int lane = tid & 31, wid = tid >> 5;
    const int g = lane >> 2, t4 = lane & 3;
    const int wm = (wid >> 2) * 64, wn = (wid & 3) * 32;

    const int ar  = tid >> 2, ac4 = (tid & 3) * 4;   // A tile loader
    const int bk  = tid >> 5, bn4 = (tid & 31) * 4;  // B tile loader

    float4 a0v = *(const float4*)(Ag + (size_t)ar * lda + ac4);
    float4 a1v = *(const float4*)(Ag + (size_t)(ar + 64) * lda + ac4);
    float4 b0v = *(const float4*)(Bg + (size_t)bk * ldb + bn4);
    float4 b1v = *(const float4*)(Bg + (size_t)(bk + 8) * ldb + bn4);

    for (int kt = 0; kt < ktiles; ++kt) {
        const int buf = kt & 1;
        *(float4*)&As[buf][ar][ac4]      = to_tf32_4(a0v);
        *(float4*)&As[buf][ar + 64][ac4] = to_tf32_4(a1v);
        *(float4*)&Bs[buf][bk][bn4]      = to_tf32_4(b0v);
        *(float4*)&Bs[buf][bk + 8][bn4]  = to_tf32_4(b1v);
        __syncthreads();
        if (kt + 1 < ktiles) {
            const float* Ap = Ag + (kt + 1) * 16;
            a0v = *(const float4*)(Ap + (size_t)ar * lda + ac4);
            a1v = *(const float4*)(Ap + (size_t)(ar + 64) * lda + ac4);
            const float* Bp = Bg + (size_t)(kt + 1) * 16 * ldb;
            b0v = *(const float4*)(Bp + (size_t)bk * ldb + bn4);
            b1v = *(const float4*)(Bp + (size_t)(bk + 8) * ldb + bn4);
        }
#pragma unroll
        for (int k0 = 0; k0 < 16; k0 += 8) {
            float a[4][4], b[4][2];
#pragma unroll
            for (int mi = 0; mi < 4; ++mi) {
                const int r = wm + mi * 16 + g;
                a[mi][0] = As[buf][r][k0 + t4];
                a[mi][1] = As[buf][r + 8][k0 + t4];
                a[mi][2] = As[buf][r][k0 + t4 + 4];
                a[mi][3] = As[buf][r + 8][k0 + t4 + 4];
            }
#pragma unroll
            for (int ni = 0; ni < 4; ++ni) {
                const int cn = wn + ni * 8 + g;
                b[ni][0] = Bs[buf][k0 + t4][cn];
                b[ni][1] = Bs[buf][k0 + t4 + 4][cn];
            }
#pragma unroll
            for (int mi = 0; mi < 4; ++mi)
#pragma unroll
                for (int ni = 0; ni < 4; ++ni)
                    mma8(acc[mi][ni], a[mi], b[ni]);
        }
    }
}

// =====================================================================
// GEMM core, B transposed (global B[n][k], k contiguous) -> C = A B^T.
// Bs layout identical to As: [2][128][20].
// =====================================================================
__device__ __forceinline__ void gemm_bt(
    const float* __restrict__ Ag, int lda,
    const float* __restrict__ Bg, int ldb,
    int ktiles, float (&acc)[4][4][4],
    float (&As)[2][128][20], float (&Bs)[2][128][20])
{
    const int tid  = threadIdx.x;
    const int lane = tid & 31, wid = tid >> 5;
    const int g = lane >> 2, t4 = lane & 3;
    const int wm = (wid >> 2) * 64, wn = (wid & 3) * 32;
    const int r0 = tid >> 2, c4 = (tid & 3) * 4;

    float4 a0v = *(const float4*)(Ag + (size_t)r0 * lda + c4);
    float4 a1v = *(const float4*)(Ag + (size_t)(r0 + 64) * lda + c4);
    float4 b0v = *(const float4*)(Bg + (size_t)r0 * ldb + c4);
    float4 b1v = *(const float4*)(Bg + (size_t)(r0 + 64) * ldb + c4);

    for (int kt = 0; kt < ktiles; ++kt) {
        const int buf = kt & 1;
        *(float4*)&As[buf][r0][c4]      = to_tf32_4(a0v);
        *(float4*)&As[buf][r0 + 64][c4] = to_tf32_4(a1v);
        *(float4*)&Bs[buf][r0][c4]      = to_tf32_4(b0v);
        *(float4*)&Bs[buf][r0 + 64][c4] = to_tf32_4(b1v);
        __syncthreads();
        if (kt + 1 < ktiles) {
            const float* Ap = Ag + (kt + 1) * 16;
            a0v = *(const float4*)(Ap + (size_t)r0 * lda + c4);
            a1v = *(const float4*)(Ap + (size_t)(r0 + 64) * lda + c4);
            const float* Bp = Bg + (kt + 1) * 16;
            b0v = *(const float4*)(Bp + (size_t)r0 * ldb + c4);
            b1v = *(const float4*)(Bp + (size_t)(r0 + 64) * ldb + c4);
        }
#pragma unroll
        for (int k0 = 0; k0 < 16; k0 += 8) {
            float a[4][4], b[4][2];
#pragma unroll
            for (int mi = 0; mi < 4; ++mi) {
                const int r = wm + mi * 16 + g;
                a[mi][0] = As[buf][r][k0 + t4];
                a[mi][1] = As[buf][r + 8][k0 + t4];
                a[mi][2] = As[buf][r][k0 + t4 + 4];
                a[mi][3] = As[buf][r + 8][k0 + t4 + 4];
            }
#pragma unroll
            for (int ni = 0; ni < 4; ++ni) {
                const int cn = wn + ni * 8 + g;
                b[ni][0] = Bs[buf][cn][k0 + t4];
                b[ni][1] = Bs[buf][cn][k0 + t4 + 4];
            }
#pragma unroll
            for (int mi = 0; mi < 4; ++mi)
#pragma unroll
                for (int ni = 0; ni < 4; ++ni)
                    mma8(acc[mi][ni], a[mi], b[ni]);
        }
    }
}

// ---------------- Kernel 1: QKV projection + bias + RoPE ----------------
__global__ __launch_bounds__(256, 2)
void qkv_mma(const float* __restrict__ x,
             const float* __restrict__ wq, const float* __restrict__ bq,
             const float* __restrict__ wk, const float* __restrict__ bk,
             const float* __restrict__ wv, const float* __restrict__ bv) {
    __shared__ float As[2][128][20];
    __shared__ float Bs[2][16][136];

    const int z = blockIdx.z;
    const int h = z / 3, t = z - 3 * h;
    const float* W; const float* bias; float* Out;
    if (t == 0)      { W = wq; bias = bq; Out = g_Q; }
    else if (t == 1) { W = wk; bias = bk; Out = g_K; }
    else             { W = wv; bias = bv; Out = g_V; }
    W    += (size_t)h * DD * DD;
    bias += h * DD;
    Out  += (size_t)h * MTOT * DD;

    const int m0 = blockIdx.y * 128, n0 = blockIdx.x * 128;

    float acc[4][4][4];
#pragma unroll
    for (int i = 0; i < 4; ++i)
#pragma unroll
        for (int j = 0; j < 4; ++j)
#pragma unroll
            for (int r = 0; r < 4; ++r) acc[i][j][r] = 0.f;

    gemm_bk(x + (size_t)m0 * DD, DD, W + n0, DD, DD / 16, acc, As, Bs);

    const int lane = threadIdx.x & 31, wid = threadIdx.x >> 5;
    const int g = lane >> 2, t4 = lane & 3;
    const int wm = (wid >> 2) * 64, wn = (wid & 3) * 32;

#pragma unroll
    for (int mi = 0; mi < 4; ++mi) {
        const int mlo = m0 + wm + mi * 16 + g;
        const int mhi = mlo + 8;
#pragma unroll
        for (int ni = 0; ni < 4; ++ni) {
            const int n = n0 + wn + ni * 8 + 2 * t4;
            float2 bb = *(const float2*)(bias + n);
            float o0 = acc[mi][ni][0] + bb.x;
            float o1 = acc[mi][ni][1] + bb.y;
            float o2 = acc[mi][ni][2] + bb.x;
            float o3 = acc[mi][ni][3] + bb.y;
            if (t < 2) {
                const int p = n >> 1;
                const int clo = mlo & (CC - 1), chi = mhi & (CC - 1);
                float cs = g_ctab[clo * 256 + p], sn = g_stab[clo * 256 + p];
                float e = o0, od = o1;
                o0 = e * cs - od * sn; o1 = e * sn + od * cs;
                cs = g_ctab[chi * 256 + p]; sn = g_stab[chi * 256 + p];
                e = o2; od = o3;
                o2 = e * cs - od * sn; o3 = e * sn + od * cs;
            }
            *(float2*)(Out + (size_t)mlo * DD + n) = make_float2(o0, o1);
            *(float2*)(Out + (size_t)mhi * DD + n) = make_float2(o2, o3);
        }
    }
}

// ---------------- Kernel 2: S = Q K^T * scale (causal tiles only) ----------------
__global__ __launch_bounds__(256, 2)
void scores_mma() {
    const int hb = blockIdx.z, qt = blockIdx.y, kt = blockIdx.x;
    if (kt > qt) return;
    __shared__ float As[2][128][20];
    __shared__ float Bs[2][128][20];

    const float* Qp = g_Q + (size_t)hb * CC * DD;
    const float* Kp = g_K + (size_t)hb * CC * DD;
    float* Sp = g_S + (size_t)hb * CC * CC;

    const int m0 = qt * 128, n0 = kt * 128;

    float acc[4][4][4];
#pragma unroll
    for (int i = 0; i < 4; ++i)
#pragma unroll
        for (int j = 0; j < 4; ++j)
#pragma unroll
            for (int r = 0; r < 4; ++r) acc[i][j][r] = 0.f;

    gemm_bt(Qp + (size_t)m0 * DD, DD, Kp + (size_t)n0 * DD, DD, DD / 16, acc, As, Bs);

    const int lane = threadIdx.x & 31, wid = threadIdx.x >> 5;
    const int g = lane >> 2, t4 = lane & 3;
    const int wm = (wid >> 2) * 64, wn = (wid & 3) * 32;
    const float scale = 0.04419417382415922f;  // 1/sqrt(512)

#pragma unroll
    for (int mi = 0; mi < 4; ++mi) {
        const int qlo = m0 + wm + mi * 16 + g;
        const int qhi = qlo + 8;
#pragma unroll
        for (int ni = 0; ni < 4; ++ni) {
            const int n = n0 + wn + ni * 8 + 2 * t4;
            float o0 = (n     <= qlo) ? acc[mi][ni][0] * scale : -1e30f;
            float o1 = (n + 1 <= qlo) ? acc[mi][ni][1] * scale : -1e30f;
            float o2 = (n     <= qhi) ? acc[mi][ni][2] * scale : -1e30f;
            float o3 = (n + 1 <= qhi) ? acc[mi][ni][3] * scale : -1e30f;
            *(float2*)(Sp + (size_t)qlo * CC + n) = make_float2(o0, o1);
            *(float2*)(Sp + (size_t)qhi * CC + n) = make_float2(o2, o3);
        }
    }
}

// ---------------- Kernel 3: row softmax (tile-aligned causal length) ----------------
__global__ __launch_bounds__(256)
void softmax_kernel() {
    int q = blockIdx.x, hb = blockIdx.y;
    float* row = g_S + (size_t)hb * CC * CC + (size_t)q * CC;
    int L = ((q >> 7) + 1) << 7;
    int tid = threadIdx.x;

    float v[8];
    float mx = -3.4e38f;
#pragma unroll
    for (int u = 0; u < 8; ++u) {
        int idx = tid + u * 256;
        float t = (idx < L) ? row[idx] : -3.4e38f;
        v[u] = t;
        mx = fmaxf(mx, t);
    }

    __shared__ float red[256];
    red[tid] = mx; __syncthreads();
    for (int o = 128; o > 0; o >>= 1) {
        if (tid < o) red[tid] = fmaxf(red[tid], red[tid + o]);
        __syncthreads();
    }
    mx = red[0];
    __syncthreads();

    float s = 0.f;
#pragma unroll
    for (int u = 0; u < 8; ++u) {
        float e = expf(v[u] - mx);
        v[u] = e;
        s += e;
    }
    red[tid] = s; __syncthreads();
    for (int o = 128; o > 0; o >>= 1) {
        if (tid < o) red[tid] += red[tid + o];
        __syncthreads();
    }
    float inv = 1.0f / red[0];

#pragma unroll
    for (int u = 0; u < 8; ++u) {
        int idx = tid + u * 256;
        if (idx < L) row[idx] = v[u] * inv;
    }
}

// ---------------- Kernel 4: O = P @ V (K extent per q-tile) ----------------
__global__ __launch_bounds__(256, 2)
void pv_mma() {
    __shared__ float As[2][128][20];
    __shared__ float Bs[2][16][136];

    const int hb = blockIdx.z, qt = blockIdx.y, nt = blockIdx.x;
    const float* P  = g_S + (size_t)hb * CC * CC;
    const float* Vp = g_V + (size_t)hb * CC * DD;

    const int m0 = qt * 128, n0 = nt * 128;
    const int ktiles = (qt + 1) * 8;

    float acc[4][4][4];
#pragma unroll
    for (int i = 0; i < 4; ++i)
#pragma unroll
        for (int j = 0; j < 4; ++j)
#pragma unroll
            for (int r = 0; r < 4; ++r) acc[i][j][r] = 0.f;

    gemm_bk(P + (size_t)m0 * CC, CC, Vp + n0, DD, ktiles, acc, As, Bs);

    const int lane = threadIdx.x & 31, wid = threadIdx.x >> 5;
    const int g = lane >> 2, t4 = lane & 3;
    const int wm = (wid >> 2) * 64, wn = (wid & 3) * 32;
    const int h = hb >> 2, b = hb & 3;

#pragma unroll
    for (int mi = 0; mi < 4; ++mi) {
        const int mlo = m0 + wm + mi * 16 + g;
        const int mhi = mlo + 8;
#pragma unroll
        for (int ni = 0; ni < 4; ++ni) {
            const int n = n0 + wn + ni * 8 + 2 * t4;
            float* plo = g_O + (size_t)(b * CC + mlo) * HD + (size_t)h * DD + n;
            float* phi = g_O + (size_t)(b * CC + mhi) * HD + (size_t)h * DD + n;
            *(float2*)plo = make_float2(acc[mi][ni][0], acc[mi][ni][1]);
            *(float2*)phi = make_float2(acc[mi][ni][2], acc[mi][ni][3]);
        }
    }
}

// ---------------- Kernel 5: final projection + bias ----------------
__global__ __launch_bounds__(256, 2)
void outproj_mma(const float* __restrict__ wo, const float* __restrict__ bo,
                 float* __restrict__ out) {
    __shared__ float As[2][128][20];
    __shared__ float Bs[2][16][136];

    const int m0 = blockIdx.y * 128, n0 = blockIdx.x * 128;

    float acc[4][4][4];
#pragma unroll
    for (int i = 0; i < 4; ++i)
#pragma unroll
        for (int j = 0; j < 4; ++j)
#pragma unroll
            for (int r = 0; r < 4; ++r) acc[i][j][r] = 0.f;

    gemm_bk(g_O + (size_t)m0 * HD, HD, wo + n0, DD, HD / 16, acc, As, Bs);

    const int lane = threadIdx.x & 31, wid = threadIdx.x >> 5;
    const int g = lane >> 2, t4 = lane & 3;
    const int wm = (wid >> 2) * 64, wn = (wid & 3) * 32;

#pragma unroll
    for (int mi = 0; mi < 4; ++mi) {
        const int mlo = m0 + wm + mi * 16 + g;
        const int mhi = mlo + 8;
#pragma unroll
        for (int ni = 0; ni < 4; ++ni) {
            const int n = n0 + wn + ni * 8 + 2 * t4;
            float2 bb = *(const float2*)(bo + n);
            *(float2*)(out + (size_t)mlo * DD + n) =
                make_float2(acc[mi][ni][0] + bb.x, acc[mi][ni][1] + bb.y);
            *(float2*)(out + (size_t)mhi * DD + n) =
                make_float2(acc[mi][ni][2] + bb.x, acc[mi][ni][3] + bb.y);
        }
    }
}

// ---------------- launch ----------------
extern "C" void kernel_launch(void* const* d_in, const int* in_sizes, int n_in,
                              void* d_out, int out_size) {
    (void)in_sizes; (void)n_in; (void)out_size;
    const float* x  = (const float*)d_in[0];
    const float* wq = (const float*)d_in[1];
    const float* bq = (const float*)d_in[2];
    const float* wk = (const float*)d_in[3];
    const float* bk = (const float*)d_in[4];
    const float* wv = (const float*)d_in[5];
    const float* bv = (const float*)d_in[6];
    const float* wo = (const float*)d_in[7];
    const float* bo = (const float*)d_in[8];
    float* out = (float*)d_out;

    rope_table_kernel<<<(CC * (DD / 2) + 255) / 256, 256>>>();
    qkv_mma<<<dim3(4, 64, 24), 256>>>(x, wq, bq, wk, bk, wv, bv);
    scores_mma<<<dim3(16, 16, 32), 256>>>();
    softmax_kernel<<<dim3(CC, 32), 256>>>();
    pv_mma<<<dim3(4, 16, 32), 256>>>();
    outproj_mma<<<dim3(4, 64, 1), 256>>>(wo, bo, out);
}

// round 9
// speedup vs baseline: 2.6476x; 1.0003x over previous
#include <cuda_runtime.h>
#include <math.h>
#include <stdint.h>

#define BB   4
#define CC   2048
#define DD   512
#define NHH  8
#define MTOT (BB * CC)      // 8192
#define HD   (NHH * DD)     // 4096

// ---------------- scratch (device globals: no allocation allowed) ----------------
__device__ float g_Q[(size_t)NHH * BB * CC * DD];   // [h][b][c][d]
__device__ float g_K[(size_t)NHH * BB * CC * DD];
__device__ float g_V[(size_t)NHH * BB * CC * DD];
__device__ float g_S[(size_t)NHH * BB * CC * CC];   // [hb][q][k]
__device__ float g_O[(size_t)MTOT * HD];            // [b*C+c][h*D+d]
__device__ float g_ctab[CC * (DD / 2)];
__device__ float g_stab[CC * (DD / 2)];

// ---------------- RoPE cos/sin table ----------------
__global__ void rope_table_kernel() {
    int idx = blockIdx.x * blockDim.x + threadIdx.x;
    if (idx >= CC * (DD / 2)) return;
    int c = idx / (DD / 2);
    int i = idx - c * (DD / 2);
    double theta = exp((-2.0 * (double)i / (double)DD) * log(10000.0));
    double ang = fmod((double)c * theta, 6.283185307179586476925287);
    float af = (float)ang;
    g_ctab[idx] = cosf(af);
    g_stab[idx] = sinf(af);
}

// ---------------- TF32 helpers ----------------
__device__ __forceinline__ float to_tf32(float x) {
    uint32_t u;
    asm("cvt.rna.tf32.f32 %0, %1;" : "=r"(u) : "f"(x));
    return __uint_as_float(u);
}
__device__ __forceinline__ float4 to_tf32_4(float4 v) {
    return make_float4(to_tf32(v.x), to_tf32(v.y), to_tf32(v.z), to_tf32(v.w));
}

__device__ __forceinline__ void mma8(float* d, const float* a, const float* b) {
    asm volatile(
        "mma.sync.aligned.m16n8k8.row.col.f32.tf32.tf32.f32 "
        "{%0,%1,%2,%3}, {%4,%5,%6,%7}, {%8,%9}, {%0,%1,%2,%3};"
        : "+f"(d[0]), "+f"(d[1]), "+f"(d[2]), "+f"(d[3])
        : "r"(__float_as_uint(a[0])), "r"(__float_as_uint(a[1])),
          "r"(__float_as_uint(a[2])), "r"(__float_as_uint(a[3])),
          "r"(__float_as_uint(b[0])), "r"(__float_as_uint(b[1])));
}

// =====================================================================
// GEMM core, B k-major (B stored [k][n], n contiguous).
// Block tile 128x128, 256 threads, 8 warps as 2(m) x 4(n), warp tile 64x32.
// As: [2][128][20] row-major (k contiguous), Bs: [2][16][136].
// =====================================================================
__device__ __forceinline__ void gemm_bk(
    const float* __restrict__ Ag, int lda,
    const float* __restrict__ Bg, int ldb,
    int ktiles, float (&acc)[4][4][4],
    float (&As)[2][128][20], float (&Bs)[2][16][136])
{
    const int tid  = threadIdx.x;
    const int lane = tid & 31, wid = tid >> 5;
    const int g = lane >> 2, t4 = lane & 3;
    const int wm = (wid >> 2) * 64, wn = (wid & 3) * 32;

    const int ar  = tid >> 2, ac4 = (tid & 3) * 4;   // A tile loader
    const int bk  = tid >> 5, bn4 = (tid & 31) * 4;  // B tile loader

    float4 a0v = *(const float4*)(Ag + (size_t)ar * lda + ac4);
    float4 a1v = *(const float4*)(Ag + (size_t)(ar + 64) * lda + ac4);
    float4 b0v = *(const float4*)(Bg + (size_t)bk * ldb + bn4);
    float4 b1v = *(const float4*)(Bg + (size_t)(bk + 8) * ldb + bn4);

    for (int kt = 0; kt < ktiles; ++kt) {
        const int buf = kt & 1;
        *(float4*)&As[buf][ar][ac4]      = to_tf32_4(a0v);
        *(float4*)&As[buf][ar + 64][ac4] = to_tf32_4(a1v);
        *(float4*)&Bs[buf][bk][bn4]      = to_tf32_4(b0v);
        *(float4*)&Bs[buf][bk + 8][bn4]  = to_tf32_4(b1v);
        __syncthreads();
        if (kt + 1 < ktiles) {
            const float* Ap = Ag + (kt + 1) * 16;
            a0v = *(const float4*)(Ap + (size_t)ar * lda + ac4);
            a1v = *(const float4*)(Ap + (size_t)(ar + 64) * lda + ac4);
            const float* Bp = Bg + (size_t)(kt + 1) * 16 * ldb;
            b0v = *(const float4*)(Bp + (size_t)bk * ldb + bn4);
            b1v = *(const float4*)(Bp + (size_t)(bk + 8) * ldb + bn4);
        }
#pragma unroll
        for (int k0 = 0; k0 < 16; k0 += 8) {
            float a[4][4], b[4][2];
#pragma unroll
            for (int mi = 0; mi < 4; ++mi) {
                const int r = wm + mi * 16 + g;
                a[mi][0] = As[buf][r][k0 + t4];
                a[mi][1] = As[buf][r + 8][k0 + t4];
                a[mi][2] = As[buf][r][k0 + t4 + 4];
                a[mi][3] = As[buf][r + 8][k0 + t4 + 4];
            }
#pragma unroll
            for (int ni = 0; ni < 4; ++ni) {
                const int cn = wn + ni * 8 + g;
                b[ni][0] = Bs[buf][k0 + t4][cn];
                b[ni][1] = Bs[buf][k0 + t4 + 4][cn];
            }
#pragma unroll
            for (int mi = 0; mi < 4; ++mi)
#pragma unroll
                for (int ni = 0; ni < 4; ++ni)
                    mma8(acc[mi][ni], a[mi], b[ni]);
        }
    }
}

// =====================================================================
// GEMM core, B transposed (global B[n][k], k contiguous) -> C = A B^T.
// Bs layout identical to As: [2][128][20].
// =====================================================================
__device__ __forceinline__ void gemm_bt(
    const float* __restrict__ Ag, int lda,
    const float* __restrict__ Bg, int ldb,
    int ktiles, float (&acc)[4][4][4],
    float (&As)[2][128][20], float (&Bs)[2][128][20])
{
    const int tid  = threadIdx.x;
    const int lane = tid & 31, wid = tid >> 5;
    const int g = lane >> 2, t4 = lane & 3;
    const int wm = (wid >> 2) * 64, wn = (wid & 3) * 32;
    const int r0 = tid >> 2, c4 = (tid & 3) * 4;

    float4 a0v = *(const float4*)(Ag + (size_t)r0 * lda + c4);
    float4 a1v = *(const float4*)(Ag + (size_t)(r0 + 64) * lda + c4);
    float4 b0v = *(const float4*)(Bg + (size_t)r0 * ldb + c4);
    float4 b1v = *(const float4*)(Bg + (size_t)(r0 + 64) * ldb + c4);

    for (int kt = 0; kt < ktiles; ++kt) {
        const int buf = kt & 1;
        *(float4*)&As[buf][r0][c4]      = to_tf32_4(a0v);
        *(float4*)&As[buf][r0 + 64][c4] = to_tf32_4(a1v);
        *(float4*)&Bs[buf][r0][c4]      = to_tf32_4(b0v);
        *(float4*)&Bs[buf][r0 + 64][c4] = to_tf32_4(b1v);
        __syncthreads();
        if (kt + 1 < ktiles) {
            const float* Ap = Ag + (kt + 1) * 16;
            a0v = *(const float4*)(Ap + (size_t)r0 * lda + c4);
            a1v = *(const float4*)(Ap + (size_t)(r0 + 64) * lda + c4);
            const float* Bp = Bg + (kt + 1) * 16;
            b0v = *(const float4*)(Bp + (size_t)r0 * ldb + c4);
            b1v = *(const float4*)(Bp + (size_t)(r0 + 64) * ldb + c4);
        }
#pragma unroll
        for (int k0 = 0; k0 < 16; k0 += 8) {
            float a[4][4], b[4][2];
#pragma unroll
            for (int mi = 0; mi < 4; ++mi) {
                const int r = wm + mi * 16 + g;
                a[mi][0] = As[buf][r][k0 + t4];
                a[mi][1] = As[buf][r + 8][k0 + t4];
                a[mi][2] = As[buf][r][k0 + t4 + 4];
                a[mi][3] = As[buf][r + 8][k0 + t4 + 4];
            }
#pragma unroll
            for (int ni = 0; ni < 4; ++ni) {
                const int cn = wn + ni * 8 + g;
                b[ni][0] = Bs[buf][cn][k0 + t4];
                b[ni][1] = Bs[buf][cn][k0 + t4 + 4];
            }
#pragma unroll
            for (int mi = 0; mi < 4; ++mi)
#pragma unroll
                for (int ni = 0; ni < 4; ++ni)
                    mma8(acc[mi][ni], a[mi], b[ni]);
        }
    }
}

// ---------------- Kernel 1: QKV projection + bias + RoPE ----------------
__global__ __launch_bounds__(256, 2)
void qkv_mma(const float* __restrict__ x,
             const float* __restrict__ wq, const float* __restrict__ bq,
             const float* __restrict__ wk, const float* __restrict__ bk,
             const float* __restrict__ wv, const float* __restrict__ bv) {
    __shared__ float As[2][128][20];
    __shared__ float Bs[2][16][136];

    const int z = blockIdx.z;
    const int h = z / 3, t = z - 3 * h;
    const float* W; const float* bias; float* Out;
    if (t == 0)      { W = wq; bias = bq; Out = g_Q; }
    else if (t == 1) { W = wk; bias = bk; Out = g_K; }
    else             { W = wv; bias = bv; Out = g_V; }
    W    += (size_t)h * DD * DD;
    bias += h * DD;
    Out  += (size_t)h * MTOT * DD;

    const int m0 = blockIdx.y * 128, n0 = blockIdx.x * 128;

    float acc[4][4][4];
#pragma unroll
    for (int i = 0; i < 4; ++i)
#pragma unroll
        for (int j = 0; j < 4; ++j)
#pragma unroll
            for (int r = 0; r < 4; ++r) acc[i][j][r] = 0.f;

    gemm_bk(x + (size_t)m0 * DD, DD, W + n0, DD, DD / 16, acc, As, Bs);

    const int lane = threadIdx.x & 31, wid = threadIdx.x >> 5;
    const int g = lane >> 2, t4 = lane & 3;
    const int wm = (wid >> 2) * 64, wn = (wid & 3) * 32;

#pragma unroll
    for (int mi = 0; mi < 4; ++mi) {
        const int mlo = m0 + wm + mi * 16 + g;
        const int mhi = mlo + 8;
#pragma unroll
        for (int ni = 0; ni < 4; ++ni) {
            const int n = n0 + wn + ni * 8 + 2 * t4;
            float2 bb = *(const float2*)(bias + n);
            float o0 = acc[mi][ni][0] + bb.x;
            float o1 = acc[mi][ni][1] + bb.y;
            float o2 = acc[mi][ni][2] + bb.x;
            float o3 = acc[mi][ni][3] + bb.y;
            if (t < 2) {
                const int p = n >> 1;
                const int clo = mlo & (CC - 1), chi = mhi & (CC - 1);
                float cs = g_ctab[clo * 256 + p], sn = g_stab[clo * 256 + p];
                float e = o0, od = o1;
                o0 = e * cs - od * sn; o1 = e * sn + od * cs;
                cs = g_ctab[chi * 256 + p]; sn = g_stab[chi * 256 + p];
                e = o2; od = o3;
                o2 = e * cs - od * sn; o3 = e * sn + od * cs;
            }
            *(float2*)(Out + (size_t)mlo * DD + n) = make_float2(o0, o1);
            *(float2*)(Out + (size_t)mhi * DD + n) = make_float2(o2, o3);
        }
    }
}

// ---------------- Kernel 2: S = Q K^T * scale (causal tiles only) ----------------
__global__ __launch_bounds__(256, 2)
void scores_mma() {
    const int hb = blockIdx.z, qt = blockIdx.y, kt = blockIdx.x;
    if (kt > qt) return;
    __shared__ float As[2][128][20];
    __shared__ float Bs[2][128][20];

    const float* Qp = g_Q + (size_t)hb * CC * DD;
    const float* Kp = g_K + (size_t)hb * CC * DD;
    float* Sp = g_S + (size_t)hb * CC * CC;

    const int m0 = qt * 128, n0 = kt * 128;

    float acc[4][4][4];
#pragma unroll
    for (int i = 0; i < 4; ++i)
#pragma unroll
        for (int j = 0; j < 4; ++j)
#pragma unroll
            for (int r = 0; r < 4; ++r) acc[i][j][r] = 0.f;

    gemm_bt(Qp + (size_t)m0 * DD, DD, Kp + (size_t)n0 * DD, DD, DD / 16, acc, As, Bs);

    const int lane = threadIdx.x & 31, wid = threadIdx.x >> 5;
    const int g = lane >> 2, t4 = lane & 3;
    const int wm = (wid >> 2) * 64, wn = (wid & 3) * 32;
    const float scale = 0.04419417382415922f;  // 1/sqrt(512)

#pragma unroll
    for (int mi = 0; mi < 4; ++mi) {
        const int qlo = m0 + wm + mi * 16 + g;
        const int qhi = qlo + 8;
#pragma unroll
        for (int ni = 0; ni < 4; ++ni) {
            const int n = n0 + wn + ni * 8 + 2 * t4;
            float o0 = (n     <= qlo) ? acc[mi][ni][0] * scale : -1e30f;
            float o1 = (n + 1 <= qlo) ? acc[mi][ni][1] * scale : -1e30f;
            float o2 = (n     <= qhi) ? acc[mi][ni][2] * scale : -1e30f;
            float o3 = (n + 1 <= qhi) ? acc[mi][ni][3] * scale : -1e30f;
            *(float2*)(Sp + (size_t)qlo * CC + n) = make_float2(o0, o1);
            *(float2*)(Sp + (size_t)qhi * CC + n) = make_float2(o2, o3);
        }
    }
}

// ---------------- Kernel 3: row softmax (tile-aligned causal length) ----------------
__global__ __launch_bounds__(256)
void softmax_kernel() {
    int q = blockIdx.x, hb = blockIdx.y;
    float* row = g_S + (size_t)hb * CC * CC + (size_t)q * CC;
    int L = ((q >> 7) + 1) << 7;
    int tid = threadIdx.x;

    float v[8];
    float mx = -3.4e38f;
#pragma unroll
    for (int u = 0; u < 8; ++u) {
        int idx = tid + u * 256;
        float t = (idx < L) ? row[idx] : -3.4e38f;
        v[u] = t;
        mx = fmaxf(mx, t);
    }

    __shared__ float red[256];
    red[tid] = mx; __syncthreads();
    for (int o = 128; o > 0; o >>= 1) {
        if (tid < o) red[tid] = fmaxf(red[tid], red[tid + o]);
        __syncthreads();
    }
    mx = red[0];
    __syncthreads();

    float s = 0.f;
#pragma unroll
    for (int u = 0; u < 8; ++u) {
        float e = expf(v[u] - mx);
        v[u] = e;
        s += e;
    }
    red[tid] = s; __syncthreads();
    for (int o = 128; o > 0; o >>= 1) {
        if (tid < o) red[tid] += red[tid + o];
        __syncthreads();
    }
    float inv = 1.0f / red[0];

#pragma unroll
    for (int u = 0; u < 8; ++u) {
        int idx = tid + u * 256;
        if (idx < L) row[idx] = v[u] * inv;
    }
}

// ---------------- Kernel 4: O = P @ V (K extent per q-tile) ----------------
__global__ __launch_bounds__(256, 2)
void pv_mma() {
    __shared__ float As[2][128][20];
    __shared__ float Bs[2][16][136];

    const int hb = blockIdx.z, qt = blockIdx.y, nt = blockIdx.x;
    const float* P  = g_S + (size_t)hb * CC * CC;
    const float* Vp = g_V + (size_t)hb * CC * DD;

    const int m0 = qt * 128, n0 = nt * 128;
    const int ktiles = (qt + 1) * 8;

    float acc[4][4][4];
#pragma unroll
    for (int i = 0; i < 4; ++i)
#pragma unroll
        for (int j = 0; j < 4; ++j)
#pragma unroll
            for (int r = 0; r < 4; ++r) acc[i][j][r] = 0.f;

    gemm_bk(P + (size_t)m0 * CC, CC, Vp + n0, DD, ktiles, acc, As, Bs);

    const int lane = threadIdx.x & 31, wid = threadIdx.x >> 5;
    const int g = lane >> 2, t4 = lane & 3;
    const int wm = (wid >> 2) * 64, wn = (wid & 3) * 32;
    const int h = hb >> 2, b = hb & 3;

#pragma unroll
    for (int mi = 0; mi < 4; ++mi) {
        const int mlo = m0 + wm + mi * 16 + g;
        const int mhi = mlo + 8;
#pragma unroll
        for (int ni = 0; ni < 4; ++ni) {
            const int n = n0 + wn + ni * 8 + 2 * t4;
            float* plo = g_O + (size_t)(b * CC + mlo) * HD + (size_t)h * DD + n;
            float* phi = g_O + (size_t)(b * CC + mhi) * HD + (size_t)h * DD + n;
            *(float2*)plo = make_float2(acc[mi][ni][0], acc[mi][ni][1]);
            *(float2*)phi = make_float2(acc[mi][ni][2], acc[mi][ni][3]);
        }
    }
}

// ---------------- Kernel 5: final projection + bias ----------------
__global__ __launch_bounds__(256, 2)
void outproj_mma(const float* __restrict__ wo, const float* __restrict__ bo,
                 float* __restrict__ out) {
    __shared__ float As[2][128][20];
    __shared__ float Bs[2][16][136];

    const int m0 = blockIdx.y * 128, n0 = blockIdx.x * 128;

    float acc[4][4][4];
#pragma unroll
    for (int i = 0; i < 4; ++i)
#pragma unroll
        for (int j = 0; j < 4; ++j)
#pragma unroll
            for (int r = 0; r < 4; ++r) acc[i][j][r] = 0.f;

    gemm_bk(g_O + (size_t)m0 * HD, HD, wo + n0, DD, HD / 16, acc, As, Bs);

    const int lane = threadIdx.x & 31, wid = threadIdx.x >> 5;
    const int g = lane >> 2, t4 = lane & 3;
    const int wm = (wid >> 2) * 64, wn = (wid & 3) * 32;

#pragma unroll
    for (int mi = 0; mi < 4; ++mi) {
        const int mlo = m0 + wm + mi * 16 + g;
        const int mhi = mlo + 8;
#pragma unroll
        for (int ni = 0; ni < 4; ++ni) {
            const int n = n0 + wn + ni * 8 + 2 * t4;
            float2 bb = *(const float2*)(bo + n);
            *(float2*)(out + (size_t)mlo * DD + n) =
                make_float2(acc[mi][ni][0] + bb.x, acc[mi][ni][1] + bb.y);
            *(float2*)(out + (size_t)mhi * DD + n) =
                make_float2(acc[mi][ni][2] + bb.x, acc[mi][ni][3] + bb.y);
        }
    }
}

// ---------------- launch ----------------
extern "C" void kernel_launch(void* const* d_in, const int* in_sizes, int n_in,
                              void* d_out, int out_size) {
    (void)in_sizes; (void)n_in; (void)out_size;
    const float* x  = (const float*)d_in[0];
    const float* wq = (const float*)d_in[1];
    const float* bq = (const float*)d_in[2];
    const float* wk = (const float*)d_in[3];
    const float* bk = (const float*)d_in[4];
    const float* wv = (const float*)d_in[5];
    const float* bv = (const float*)d_in[6];
    const float* wo = (const float*)d_in[7];
    const float* bo = (const float*)d_in[8];
    float* out = (float*)d_out;

    rope_table_kernel<<<(CC * (DD / 2) + 255) / 256, 256>>>();
    qkv_mma<<<dim3(4, 64, 24), 256>>>(x, wq, bq, wk, bk, wv, bv);
    scores_mma<<<dim3(16, 16, 32), 256>>>();
    softmax_kernel<<<dim3(CC, 32), 256>>>();
    pv_mma<<<dim3(4, 16, 32), 256>>>();
    outproj_mma<<<dim3(4, 64, 1), 256>>>(wo, bo, out);
}